// round 3
// baseline (speedup 1.0000x reference)
#include <cuda_runtime.h>
#include <cuda_bf16.h>
#include <math.h>
#include <stdint.h>

#define T_TOK 2048
#define H_DIM 1024
#define F_DIM 4096
#define N_EXP 8
#define NSLOT (T_TOK * 2)

#define AST  24    // A smem row stride (16 elems + 8 pad) = 48B
#define BST  72    // B smem row stride (64 elems + 8 pad) = 144B
#define BSTD 136   // down B smem row stride (128 elems + 8 pad) = 272B

// ---------------- scratch (__device__ globals) ------------------------------
__device__ int      g_count[N_EXP];
__device__ int      g_offset[N_EXP];
__device__ int      g_tok_e[NSLOT];
__device__ float    g_tok_w[NSLOT];
__device__ int      g_tok_rank[NSLOT];
__device__ int      g_slot_token[NSLOT];
__device__ int      g_slot_of[NSLOT];
__device__ uint16_t g_xh[(size_t)T_TOK * H_DIM];
__device__ uint16_t g_xl[(size_t)T_TOK * H_DIM];
__device__ uint16_t g_wgh[(size_t)N_EXP * H_DIM * F_DIM];
__device__ uint16_t g_wgl[(size_t)N_EXP * H_DIM * F_DIM];
__device__ uint16_t g_wuh[(size_t)N_EXP * H_DIM * F_DIM];
__device__ uint16_t g_wul[(size_t)N_EXP * H_DIM * F_DIM];
__device__ uint16_t g_wdh[(size_t)N_EXP * F_DIM * H_DIM];
__device__ uint16_t g_wdl[(size_t)N_EXP * F_DIM * H_DIM];
__device__ uint16_t g_acth[(size_t)NSLOT * F_DIM];
__device__ uint16_t g_actl[(size_t)NSLOT * F_DIM];
__device__ float    g_part[(size_t)NSLOT * H_DIM];

// ---------------- helpers ---------------------------------------------------
__device__ __forceinline__ uint32_t smem_u32(const void* p) {
    return (uint32_t)__cvta_generic_to_shared(p);
}
__device__ __forceinline__ void cpa16(void* dst, const void* src) {
    asm volatile("cp.async.cg.shared.global [%0], [%1], 16;"
                 :: "r"(smem_u32(dst)), "l"(src));
}
__device__ __forceinline__ void cp_commit() { asm volatile("cp.async.commit_group;"); }
__device__ __forceinline__ void cp_wait1()  { asm volatile("cp.async.wait_group 1;"); }
__device__ __forceinline__ void cp_wait0()  { asm volatile("cp.async.wait_group 0;"); }

__device__ __forceinline__ void ldsm_x4(uint32_t* r, uint32_t addr) {
    asm volatile("ldmatrix.sync.aligned.m8n8.x4.shared.b16 {%0,%1,%2,%3},[%4];"
                 : "=r"(r[0]), "=r"(r[1]), "=r"(r[2]), "=r"(r[3]) : "r"(addr));
}
__device__ __forceinline__ void ldsm_x2t(uint32_t* r, uint32_t addr) {
    asm volatile("ldmatrix.sync.aligned.m8n8.x2.trans.shared.b16 {%0,%1},[%2];"
                 : "=r"(r[0]), "=r"(r[1]) : "r"(addr));
}
__device__ __forceinline__ void mma_bf16(float* c, const uint32_t* a, const uint32_t* b) {
    asm volatile(
        "mma.sync.aligned.m16n8k16.row.col.f32.bf16.bf16.f32 "
        "{%0,%1,%2,%3},{%4,%5,%6,%7},{%8,%9},{%0,%1,%2,%3};"
        : "+f"(c[0]), "+f"(c[1]), "+f"(c[2]), "+f"(c[3])
        : "r"(a[0]), "r"(a[1]), "r"(a[2]), "r"(a[3]), "r"(b[0]), "r"(b[1]));
}
__device__ __forceinline__ void split2(float v0, float v1, uint32_t& h, uint32_t& l) {
    __nv_bfloat16 h0 = __float2bfloat16_rn(v0);
    __nv_bfloat16 h1 = __float2bfloat16_rn(v1);
    __nv_bfloat16 l0 = __float2bfloat16_rn(v0 - __bfloat162float(h0));
    __nv_bfloat16 l1 = __float2bfloat16_rn(v1 - __bfloat162float(h1));
    h = (uint32_t)*(uint16_t*)&h0 | ((uint32_t)*(uint16_t*)&h1 << 16);
    l = (uint32_t)*(uint16_t*)&l0 | ((uint32_t)*(uint16_t*)&l1 << 16);
}

// ---------------- split kernels (one pass, fp32 -> bf16 hi/lo) --------------
__global__ void split_x_kernel(const float* __restrict__ src) {
    int i = blockIdx.x * blockDim.x + threadIdx.x;
    float4 v = ((const float4*)src)[i];
    uint32_t h0, l0, h1, l1;
    split2(v.x, v.y, h0, l0);
    split2(v.z, v.w, h1, l1);
    ((uint2*)g_xh)[i] = make_uint2(h0, h1);
    ((uint2*)g_xl)[i] = make_uint2(l0, l1);
}
__global__ void split_wg_kernel(const float* __restrict__ src) {
    size_t i = (size_t)blockIdx.x * blockDim.x + threadIdx.x;
    float4 v = ((const float4*)src)[i];
    uint32_t h0, l0, h1, l1;
    split2(v.x, v.y, h0, l0);
    split2(v.z, v.w, h1, l1);
    ((uint2*)g_wgh)[i] = make_uint2(h0, h1);
    ((uint2*)g_wgl)[i] = make_uint2(l0, l1);
}
__global__ void split_wu_kernel(const float* __restrict__ src) {
    size_t i = (size_t)blockIdx.x * blockDim.x + threadIdx.x;
    float4 v = ((const float4*)src)[i];
    uint32_t h0, l0, h1, l1;
    split2(v.x, v.y, h0, l0);
    split2(v.z, v.w, h1, l1);
    ((uint2*)g_wuh)[i] = make_uint2(h0, h1);
    ((uint2*)g_wul)[i] = make_uint2(l0, l1);
}
__global__ void split_wd_kernel(const float* __restrict__ src) {
    size_t i = (size_t)blockIdx.x * blockDim.x + threadIdx.x;
    float4 v = ((const float4*)src)[i];
    uint32_t h0, l0, h1, l1;
    split2(v.x, v.y, h0, l0);
    split2(v.z, v.w, h1, l1);
    ((uint2*)g_wdh)[i] = make_uint2(h0, h1);
    ((uint2*)g_wdl)[i] = make_uint2(l0, l1);
}

// ---------------- kernel 0: zero expert counters ----------------------------
__global__ void zero_counts_kernel() {
    if (threadIdx.x < N_EXP) g_count[threadIdx.x] = 0;
}

// ---------------- kernel 1: router (one warp per token) ---------------------
__global__ void router_kernel(const float* __restrict__ x,
                              const float* __restrict__ gw) {
    int gwarp = (blockIdx.x * blockDim.x + threadIdx.x) >> 5;
    int lane  = threadIdx.x & 31;
    if (gwarp >= T_TOK) return;
    const float* xr = x + (size_t)gwarp * H_DIM;

    float acc[N_EXP];
#pragma unroll
    for (int e = 0; e < N_EXP; e++) acc[e] = 0.f;
    for (int h = lane; h < H_DIM; h += 32) {
        float xv = xr[h];
        const float* g = gw + h * N_EXP;
#pragma unroll
        for (int e = 0; e < N_EXP; e++) acc[e] += xv * g[e];
    }
#pragma unroll
    for (int e = 0; e < N_EXP; e++) {
#pragma unroll
        for (int off = 16; off > 0; off >>= 1)
            acc[e] += __shfl_xor_sync(0xffffffffu, acc[e], off);
    }
    if (lane == 0) {
        float m = acc[0];
#pragma unroll
        for (int e = 1; e < N_EXP; e++) m = fmaxf(m, acc[e]);
        float p[N_EXP], s = 0.f;
#pragma unroll
        for (int e = 0; e < N_EXP; e++) { p[e] = expf(acc[e] - m); s += p[e]; }
        float inv = 1.f / s;
#pragma unroll
        for (int e = 0; e < N_EXP; e++) p[e] *= inv;

        int i0 = 0;
#pragma unroll
        for (int e = 1; e < N_EXP; e++) if (p[e] > p[i0]) i0 = e;
        int i1 = (i0 == 0) ? 1 : 0;
#pragma unroll
        for (int e = 0; e < N_EXP; e++)
            if (e != i0 && p[e] > p[i1]) i1 = e;

        float eb = expf(p[i1] - p[i0]);
        float w0 = 1.f / (1.f + eb);
        float w1 = eb * w0;

        int r0 = atomicAdd(&g_count[i0], 1);
        int r1 = atomicAdd(&g_count[i1], 1);
        g_tok_e[gwarp * 2 + 0]    = i0;
        g_tok_e[gwarp * 2 + 1]    = i1;
        g_tok_w[gwarp * 2 + 0]    = w0;
        g_tok_w[gwarp * 2 + 1]    = w1;
        g_tok_rank[gwarp * 2 + 0] = r0;
        g_tok_rank[gwarp * 2 + 1] = r1;
    }
}

// ---------------- kernel 2: prefix offsets + scatter slot map ---------------
__global__ void scan_scatter_kernel() {
    __shared__ int soff[N_EXP];
    if (threadIdx.x == 0) {
        int s = 0;
        for (int e = 0; e < N_EXP; e++) { soff[e] = s; g_offset[e] = s; s += g_count[e]; }
    }
    __syncthreads();
    for (int t = threadIdx.x; t < T_TOK; t += blockDim.x) {
#pragma unroll
        for (int k = 0; k < 2; k++) {
            int e = g_tok_e[t * 2 + k];
            int slot = soff[e] + g_tok_rank[t * 2 + k];
            g_slot_token[slot] = t;
            g_slot_of[t * 2 + k] = slot;
        }
    }
}

// ---------------- kernel 3: fused gate+up GEMM + SwiGLU (pre-split bf16) ----
// block 128(M) x 64(N), BK=16, double-buffered cp.async; 8 warps 4x2, warp 32x32
__global__ void __launch_bounds__(256)
gateup_kernel() {
    int e = blockIdx.z;
    int n = g_count[e];
    int rowbase = blockIdx.y * 128;
    if (rowbase >= n) return;
    int off = g_offset[e];
    int f0  = blockIdx.x * 64;
    size_t we = (size_t)e * H_DIM * F_DIM;

    __shared__ __align__(16) uint16_t sAh[2][128 * AST];
    __shared__ __align__(16) uint16_t sAl[2][128 * AST];
    __shared__ __align__(16) uint16_t sB[2][4][16 * BST];

    int tid = threadIdx.x, lane = tid & 31, wid = tid >> 5;
    int warp_m = wid >> 1, warp_n = wid & 1;

    // A gather (2 threads/row, 8 elems = 16B each)
    int arow = tid >> 1, ahalf = tid & 1;
    int srow = rowbase + arow; if (srow > n - 1) srow = n - 1;
    size_t xoff = (size_t)g_slot_token[off + srow] * H_DIM + ahalf * 8;
    const uint16_t* gah = g_xh + xoff;
    const uint16_t* gal = g_xl + xoff;
    uint32_t adst = arow * AST + ahalf * 8;

    // B loaders: 2 chunks/thread over 4 matrices x 16 rows x 8 colchunks
    const uint16_t* bsrc[2];
    int bmat[2]; uint32_t bdst[2];
#pragma unroll
    for (int c = 0; c < 2; c++) {
        int idx = tid + c * 256;
        int brow = idx & 15, t = idx >> 4;
        int mat = t & 3, col = (t >> 2) * 8;
        const uint16_t* base = (mat == 0) ? g_wgh : (mat == 1) ? g_wgl
                             : (mat == 2) ? g_wuh : g_wul;
        bsrc[c] = base + we + (size_t)brow * F_DIM + f0 + col;
        bmat[c] = mat;
        bdst[c] = brow * BST + col;
    }

    float accg[2][4][4], accu[2][4][4];
#pragma unroll
    for (int i = 0; i < 2; i++)
#pragma unroll
        for (int j = 0; j < 4; j++)
#pragma unroll
            for (int q = 0; q < 4; q++) { accg[i][j][q] = 0.f; accu[i][j][q] = 0.f; }

    auto load_tile = [&](int st, int kt) {
        cpa16(&sAh[st][adst], gah + kt * 16);
        cpa16(&sAl[st][adst], gal + kt * 16);
        size_t ko = (size_t)kt * 16 * F_DIM;
        cpa16(&sB[st][bmat[0]][bdst[0]], bsrc[0] + ko);
        cpa16(&sB[st][bmat[1]][bdst[1]], bsrc[1] + ko);
        cp_commit();
    };

    load_tile(0, 0);
    const int KT = H_DIM / 16;
#pragma unroll 1
    for (int kt = 0; kt < KT; kt++) {
        int st = kt & 1;
        if (kt + 1 < KT) { load_tile(st ^ 1, kt + 1); cp_wait1(); }
        else cp_wait0();
        __syncthreads();

        uint32_t ah[2][4], al[2][4];
        int r8 = lane & 7, tsel = lane >> 3;
        int acol = (tsel >> 1) * 8;
#pragma unroll
        for (int mt = 0; mt < 2; mt++) {
            int ar = warp_m * 32 + mt * 16 + r8 + (tsel & 1) * 8;
            ldsm_x4(ah[mt], smem_u32(&sAh[st][ar * AST + acol]));
            ldsm_x4(al[mt], smem_u32(&sAl[st][ar * AST + acol]));
        }
        int bkr = (lane & 7) + ((lane >> 3) & 1) * 8;
#pragma unroll
        for (int nt = 0; nt < 4; nt++) {
            int nn = warp_n * 32 + nt * 8;
            uint32_t bgh[2], bgl[2], buh[2], bul[2];
            ldsm_x2t(bgh, smem_u32(&sB[st][0][bkr * BST + nn]));
            ldsm_x2t(bgl, smem_u32(&sB[st][1][bkr * BST + nn]));
            ldsm_x2t(buh, smem_u32(&sB[st][2][bkr * BST + nn]));
            ldsm_x2t(bul, smem_u32(&sB[st][3][bkr * BST + nn]));
#pragma unroll
            for (int mt = 0; mt < 2; mt++) {
                mma_bf16(accg[mt][nt], ah[mt], bgh);
                mma_bf16(accg[mt][nt], ah[mt], bgl);
                mma_bf16(accg[mt][nt], al[mt], bgh);
                mma_bf16(accu[mt][nt], ah[mt], buh);
                mma_bf16(accu[mt][nt], ah[mt], bul);
                mma_bf16(accu[mt][nt], al[mt], buh);
            }
        }
        __syncthreads();
    }

    // epilogue: SwiGLU + split-store activations
    int gq = lane >> 2, tq = lane & 3;
#pragma unroll
    for (int mt = 0; mt < 2; mt++)
#pragma unroll
        for (int nt = 0; nt < 4; nt++) {
            int fc = f0 + warp_n * 32 + nt * 8 + tq * 2;
#pragma unroll
            for (int h2 = 0; h2 < 2; h2++) {
                int row = rowbase + warp_m * 32 + mt * 16 + gq + h2 * 8;
                if (row < n) {
                    float g0 = accg[mt][nt][h2 * 2],     g1 = accg[mt][nt][h2 * 2 + 1];
                    float u0 = accu[mt][nt][h2 * 2],     u1 = accu[mt][nt][h2 * 2 + 1];
                    float v0 = g0 / (1.f + expf(-g0)) * u0;
                    float v1 = g1 / (1.f + expf(-g1)) * u1;
                    uint32_t hh, ll;
                    split2(v0, v1, hh, ll);
                    size_t base = (size_t)(off + row) * F_DIM + fc;
                    *(uint32_t*)(g_acth + base) = hh;
                    *(uint32_t*)(g_actl + base) = ll;
                }
            }
        }
}

// ---------------- kernel 4: down GEMM (pre-split bf16) ----------------------
// block 128(M) x 128(N), BK=16; 8 warps 4x2, warp 32x64
__global__ void __launch_bounds__(256)
down_kernel() {
    int e = blockIdx.z;
    int n = g_count[e];
    int rowbase = blockIdx.y * 128;
    if (rowbase >= n) return;
    int off = g_offset[e];
    int h0  = blockIdx.x * 128;
    size_t we = (size_t)e * F_DIM * H_DIM;

    __shared__ __align__(16) uint16_t sAh[2][128 * AST];
    __shared__ __align__(16) uint16_t sAl[2][128 * AST];
    __shared__ __align__(16) uint16_t sB[2][2][16 * BSTD];

    int tid = threadIdx.x, lane = tid & 31, wid = tid >> 5;
    int warp_m = wid >> 1, warp_n = wid & 1;

    int arow = tid >> 1, ahalf = tid & 1;
    int srow = rowbase + arow; if (srow > n - 1) srow = n - 1;
    size_t aoff = (size_t)(off + srow) * F_DIM + ahalf * 8;
    const uint16_t* gah = g_acth + aoff;
    const uint16_t* gal = g_actl + aoff;
    uint32_t adst = arow * AST + ahalf * 8;

    // B loaders: 2 chunks/thread over 2 matrices x 16 rows x 16 colchunks
    const uint16_t* bsrc[2];
    int bmat[2]; uint32_t bdst[2];
#pragma unroll
    for (int c = 0; c < 2; c++) {
        int idx = tid + c * 256;
        int brow = idx & 15, t = idx >> 4;
        int mat = t & 1, col = (t >> 1) * 8;
        const uint16_t* base = (mat == 0) ? g_wdh : g_wdl;
        bsrc[c] = base + we + (size_t)brow * H_DIM + h0 + col;
        bmat[c] = mat;
        bdst[c] = brow * BSTD + col;
    }

    float acc[2][8][4];
#pragma unroll
    for (int i = 0; i < 2; i++)
#pragma unroll
        for (int j = 0; j < 8; j++)
#pragma unroll
            for (int q = 0; q < 4; q++) acc[i][j][q] = 0.f;

    auto load_tile = [&](int st, int kt) {
        cpa16(&sAh[st][adst], gah + kt * 16);
        cpa16(&sAl[st][adst], gal + kt * 16);
        size_t ko = (size_t)kt * 16 * H_DIM;
        cpa16(&sB[st][bmat[0]][bdst[0]], bsrc[0] + ko);
        cpa16(&sB[st][bmat[1]][bdst[1]], bsrc[1] + ko);
        cp_commit();
    };

    load_tile(0, 0);
    const int KT = F_DIM / 16;
#pragma unroll 1
    for (int kt = 0; kt < KT; kt++) {
        int st = kt & 1;
        if (kt + 1 < KT) { load_tile(st ^ 1, kt + 1); cp_wait1(); }
        else cp_wait0();
        __syncthreads();

        uint32_t ah[2][4], al[2][4];
        int r8 = lane & 7, tsel = lane >> 3;
        int acol = (tsel >> 1) * 8;
#pragma unroll
        for (int mt = 0; mt < 2; mt++) {
            int ar = warp_m * 32 + mt * 16 + r8 + (tsel & 1) * 8;
            ldsm_x4(ah[mt], smem_u32(&sAh[st][ar * AST + acol]));
            ldsm_x4(al[mt], smem_u32(&sAl[st][ar * AST + acol]));
        }
        int bkr = (lane & 7) + ((lane >> 3) & 1) * 8;
#pragma unroll
        for (int nt = 0; nt < 8; nt++) {
            int nn = warp_n * 64 + nt * 8;
            uint32_t bh[2], bl[2];
            ldsm_x2t(bh, smem_u32(&sB[st][0][bkr * BSTD + nn]));
            ldsm_x2t(bl, smem_u32(&sB[st][1][bkr * BSTD + nn]));
#pragma unroll
            for (int mt = 0; mt < 2; mt++) {
                mma_bf16(acc[mt][nt], ah[mt], bh);
                mma_bf16(acc[mt][nt], ah[mt], bl);
                mma_bf16(acc[mt][nt], al[mt], bh);
            }
        }
        __syncthreads();
    }

    int gq = lane >> 2, tq = lane & 3;
#pragma unroll
    for (int mt = 0; mt < 2; mt++)
#pragma unroll
        for (int nt = 0; nt < 8; nt++) {
            int hc = h0 + warp_n * 64 + nt * 8 + tq * 2;
#pragma unroll
            for (int h2 = 0; h2 < 2; h2++) {
                int row = rowbase + warp_m * 32 + mt * 16 + gq + h2 * 8;
                if (row < n) {
                    float2 v = make_float2(acc[mt][nt][h2 * 2], acc[mt][nt][h2 * 2 + 1]);
                    *(float2*)(g_part + (size_t)(off + row) * H_DIM + hc) = v;
                }
            }
        }
}

// ---------------- kernel 5: weighted combine --------------------------------
__global__ void combine_kernel(float* __restrict__ out) {
    int idx = blockIdx.x * blockDim.x + threadIdx.x;
    if (idx >= T_TOK * H_DIM) return;
    int t = idx >> 10;
    int h = idx & 1023;
    int   s0 = g_slot_of[t * 2 + 0];
    int   s1 = g_slot_of[t * 2 + 1];
    float w0 = g_tok_w[t * 2 + 0];
    float w1 = g_tok_w[t * 2 + 1];
    out[idx] = w0 * g_part[(size_t)s0 * H_DIM + h] +
               w1 * g_part[(size_t)s1 * H_DIM + h];
}

// ---------------- launch ----------------------------------------------------
extern "C" void kernel_launch(void* const* d_in, const int* in_sizes, int n_in,
                              void* d_out, int out_size) {
    const float* x      = (const float*)d_in[0];
    const float* gate_w = (const float*)d_in[1];
    const float* w_gate = (const float*)d_in[2];
    const float* w_up   = (const float*)d_in[3];
    const float* w_down = (const float*)d_in[4];
    float* out = (float*)d_out;

    zero_counts_kernel<<<1, 32>>>();
    router_kernel<<<T_TOK / 8, 256>>>(x, gate_w);
    scan_scatter_kernel<<<1, 256>>>();

    split_x_kernel<<<(T_TOK * H_DIM / 4) / 256, 256>>>(x);
    const int WBLK = (int)(((size_t)N_EXP * H_DIM * F_DIM / 4) / 256);  // 32768
    split_wg_kernel<<<WBLK, 256>>>(w_gate);
    split_wu_kernel<<<WBLK, 256>>>(w_up);
    split_wd_kernel<<<WBLK, 256>>>(w_down);

    gateup_kernel<<<dim3(F_DIM / 64, NSLOT / 128, N_EXP), 256>>>();
    down_kernel<<<dim3(H_DIM / 128, NSLOT / 128, N_EXP), 256>>>();
    combine_kernel<<<(T_TOK * H_DIM) / 256, 256>>>(out);
}

// round 6
// speedup vs baseline: 1.0094x; 1.0094x over previous
#include <cuda_runtime.h>
#include <cuda_bf16.h>
#include <math.h>
#include <stdint.h>

#define T_TOK 2048
#define H_DIM 1024
#define F_DIM 4096
#define N_EXP 8
#define NSLOT (T_TOK * 2)

#define AST  24    // A smem row stride elems (16+8 pad)
#define BST  72    // gateup B row stride (64+8)
#define BSTD 136   // down B row stride (128+8)

// gateup stage: Ah 6144 + Al 6144 + 4 B mats * 2304 = 21504 B
#define GU_STAGE 21504
#define GU_SMEM  (3 * GU_STAGE)
// down stage: Ah 6144 + Al 6144 + 2 B mats * 4352 = 20992 B
#define DN_STAGE 20992
#define DN_SMEM  (3 * DN_STAGE)

// ---------------- scratch ----------------------------------------------------
__device__ int      g_count[N_EXP];
__device__ int      g_offset[N_EXP];
__device__ int      g_tok_e[NSLOT];
__device__ float    g_tok_w[NSLOT];
__device__ int      g_tok_rank[NSLOT];
__device__ int      g_slot_token[NSLOT];
__device__ int      g_slot_of[NSLOT];
__device__ uint16_t g_xh[(size_t)T_TOK * H_DIM];
__device__ uint16_t g_xl[(size_t)T_TOK * H_DIM];
__device__ uint16_t g_wgh[(size_t)N_EXP * H_DIM * F_DIM];
__device__ uint16_t g_wgl[(size_t)N_EXP * H_DIM * F_DIM];
__device__ uint16_t g_wuh[(size_t)N_EXP * H_DIM * F_DIM];
__device__ uint16_t g_wul[(size_t)N_EXP * H_DIM * F_DIM];
__device__ uint16_t g_wdh[(size_t)N_EXP * F_DIM * H_DIM];
__device__ uint16_t g_wdl[(size_t)N_EXP * F_DIM * H_DIM];
__device__ uint16_t g_acth[(size_t)NSLOT * F_DIM];
__device__ uint16_t g_actl[(size_t)NSLOT * F_DIM];
__device__ float    g_part[(size_t)NSLOT * H_DIM];

// ---------------- helpers ----------------------------------------------------
__device__ __forceinline__ uint32_t smem_u32(const void* p) {
    return (uint32_t)__cvta_generic_to_shared(p);
}
__device__ __forceinline__ void cpa16(void* dst, const void* src) {
    asm volatile("cp.async.cg.shared.global [%0], [%1], 16;"
                 :: "r"(smem_u32(dst)), "l"(src));
}
__device__ __forceinline__ void cp_commit() { asm volatile("cp.async.commit_group;"); }
__device__ __forceinline__ void cp_wait1()  { asm volatile("cp.async.wait_group 1;"); }
__device__ __forceinline__ void cp_wait0()  { asm volatile("cp.async.wait_group 0;"); }

__device__ __forceinline__ void ldsm_x4(uint32_t* r, uint32_t addr) {
    asm volatile("ldmatrix.sync.aligned.m8n8.x4.shared.b16 {%0,%1,%2,%3},[%4];"
                 : "=r"(r[0]), "=r"(r[1]), "=r"(r[2]), "=r"(r[3]) : "r"(addr));
}
__device__ __forceinline__ void ldsm_x2t(uint32_t* r, uint32_t addr) {
    asm volatile("ldmatrix.sync.aligned.m8n8.x2.trans.shared.b16 {%0,%1},[%2];"
                 : "=r"(r[0]), "=r"(r[1]) : "r"(addr));
}
__device__ __forceinline__ void mma_bf16(float* c, const uint32_t* a, const uint32_t* b) {
    asm volatile(
        "mma.sync.aligned.m16n8k16.row.col.f32.bf16.bf16.f32 "
        "{%0,%1,%2,%3},{%4,%5,%6,%7},{%8,%9},{%0,%1,%2,%3};"
        : "+f"(c[0]), "+f"(c[1]), "+f"(c[2]), "+f"(c[3])
        : "r"(a[0]), "r"(a[1]), "r"(a[2]), "r"(a[3]), "r"(b[0]), "r"(b[1]));
}
__device__ __forceinline__ void split2(float v0, float v1, uint32_t& h, uint32_t& l) {
    __nv_bfloat16 h0 = __float2bfloat16_rn(v0);
    __nv_bfloat16 h1 = __float2bfloat16_rn(v1);
    __nv_bfloat16 l0 = __float2bfloat16_rn(v0 - __bfloat162float(h0));
    __nv_bfloat16 l1 = __float2bfloat16_rn(v1 - __bfloat162float(h1));
    h = (uint32_t)*(uint16_t*)&h0 | ((uint32_t)*(uint16_t*)&h1 << 16);
    l = (uint32_t)*(uint16_t*)&l0 | ((uint32_t)*(uint16_t*)&l1 << 16);
}

// ---------------- routing kernels --------------------------------------------
__global__ void zero_counts_kernel() {
    if (threadIdx.x < N_EXP) g_count[threadIdx.x] = 0;
}

__global__ void router_kernel(const float* __restrict__ x,
                              const float* __restrict__ gw) {
    int gwarp = (blockIdx.x * blockDim.x + threadIdx.x) >> 5;
    int lane  = threadIdx.x & 31;
    if (gwarp >= T_TOK) return;
    const float* xr = x + (size_t)gwarp * H_DIM;
    float acc[N_EXP];
#pragma unroll
    for (int e = 0; e < N_EXP; e++) acc[e] = 0.f;
    for (int h = lane; h < H_DIM; h += 32) {
        float xv = xr[h];
        const float* g = gw + h * N_EXP;
#pragma unroll
        for (int e = 0; e < N_EXP; e++) acc[e] += xv * g[e];
    }
#pragma unroll
    for (int e = 0; e < N_EXP; e++) {
#pragma unroll
        for (int off = 16; off > 0; off >>= 1)
            acc[e] += __shfl_xor_sync(0xffffffffu, acc[e], off);
    }
    if (lane == 0) {
        float m = acc[0];
#pragma unroll
        for (int e = 1; e < N_EXP; e++) m = fmaxf(m, acc[e]);
        float p[N_EXP], s = 0.f;
#pragma unroll
        for (int e = 0; e < N_EXP; e++) { p[e] = expf(acc[e] - m); s += p[e]; }
        float inv = 1.f / s;
#pragma unroll
        for (int e = 0; e < N_EXP; e++) p[e] *= inv;
        int i0 = 0;
#pragma unroll
        for (int e = 1; e < N_EXP; e++) if (p[e] > p[i0]) i0 = e;
        int i1 = (i0 == 0) ? 1 : 0;
#pragma unroll
        for (int e = 0; e < N_EXP; e++)
            if (e != i0 && p[e] > p[i1]) i1 = e;
        float eb = expf(p[i1] - p[i0]);
        float w0 = 1.f / (1.f + eb);
        float w1 = eb * w0;
        int r0 = atomicAdd(&g_count[i0], 1);
        int r1 = atomicAdd(&g_count[i1], 1);
        g_tok_e[gwarp * 2 + 0]    = i0;
        g_tok_e[gwarp * 2 + 1]    = i1;
        g_tok_w[gwarp * 2 + 0]    = w0;
        g_tok_w[gwarp * 2 + 1]    = w1;
        g_tok_rank[gwarp * 2 + 0] = r0;
        g_tok_rank[gwarp * 2 + 1] = r1;
    }
}

__global__ void scan_scatter_kernel() {
    __shared__ int soff[N_EXP];
    if (threadIdx.x == 0) {
        int s = 0;
        for (int e = 0; e < N_EXP; e++) { soff[e] = s; g_offset[e] = s; s += g_count[e]; }
    }
    __syncthreads();
    for (int t = threadIdx.x; t < T_TOK; t += blockDim.x) {
#pragma unroll
        for (int k = 0; k < 2; k++) {
            int e = g_tok_e[t * 2 + k];
            int slot = soff[e] + g_tok_rank[t * 2 + k];
            g_slot_token[slot] = t;
            g_slot_of[t * 2 + k] = slot;
        }
    }
}

// ---------------- split kernels ----------------------------------------------
__global__ void split_x_kernel(const float* __restrict__ src) {
    int i = blockIdx.x * blockDim.x + threadIdx.x;
    float4 v = ((const float4*)src)[i];
    uint32_t h0, l0, h1, l1;
    split2(v.x, v.y, h0, l0);
    split2(v.z, v.w, h1, l1);
    ((uint2*)g_xh)[i] = make_uint2(h0, h1);
    ((uint2*)g_xl)[i] = make_uint2(l0, l1);
}

__global__ void __launch_bounds__(256)
split_weights_kernel(const float* __restrict__ wg,
                     const float* __restrict__ wu,
                     const float* __restrict__ wd) {
    const size_t N8 = (size_t)N_EXP * H_DIM * F_DIM / 8;
    size_t stride = (size_t)gridDim.x * blockDim.x;
    for (size_t i = (size_t)blockIdx.x * blockDim.x + threadIdx.x; i < N8; i += stride) {
#pragma unroll
        for (int m = 0; m < 3; m++) {
            const float* src = (m == 0) ? wg : (m == 1) ? wu : wd;
            uint16_t* dh = (m == 0) ? g_wgh : (m == 1) ? g_wuh : g_wdh;
            uint16_t* dl = (m == 0) ? g_wgl : (m == 1) ? g_wul : g_wdl;
            float4 a = ((const float4*)src)[i * 2];
            float4 b = ((const float4*)src)[i * 2 + 1];
            uint32_t h[4], l[4];
            split2(a.x, a.y, h[0], l[0]);
            split2(a.z, a.w, h[1], l[1]);
            split2(b.x, b.y, h[2], l[2]);
            split2(b.z, b.w, h[3], l[3]);
            ((uint4*)dh)[i] = *(uint4*)h;
            ((uint4*)dl)[i] = *(uint4*)l;
        }
    }
}

// ---------------- gateup GEMM: 128x64, BK=16, 3-stage, 2 CTA/SM --------------
__global__ void __launch_bounds__(256, 2)
gateup_kernel() {
    extern __shared__ char smem[];
    int e = blockIdx.z;
    int n = g_count[e];
    int rowbase = blockIdx.y * 128;
    if (rowbase >= n) return;
    int off = g_offset[e];
    int f0  = blockIdx.x * 64;
    size_t we = (size_t)e * H_DIM * F_DIM;

    int tid = threadIdx.x, lane = tid & 31, wid = tid >> 5;
    int warp_m = wid >> 1, warp_n = wid & 1;

    // A gather
    int arow = tid >> 1, ahalf = tid & 1;
    int srow = rowbase + arow; if (srow > n - 1) srow = n - 1;
    size_t xoff = (size_t)g_slot_token[off + srow] * H_DIM + ahalf * 8;
    const uint16_t* gah = g_xh + xoff;
    const uint16_t* gal = g_xl + xoff;
    uint32_t adst = (uint32_t)(arow * AST + ahalf * 8) * 2;

    // B: 2 chunks/thread over 4 mats x 16 rows x 8 colchunks
    const uint16_t* bsrc[2];
    uint32_t bdst[2];
#pragma unroll
    for (int c = 0; c < 2; c++) {
        int idx = tid + c * 256;
        int brow = idx & 15, t = idx >> 4;
        int mat = t & 3, col = (t >> 2) * 8;
        const uint16_t* base = (mat == 0) ? g_wgh : (mat == 1) ? g_wgl
                             : (mat == 2) ? g_wuh : g_wul;
        bsrc[c] = base + we + (size_t)brow * F_DIM + f0 + col;
        bdst[c] = 12288 + mat * 2304 + (uint32_t)(brow * BST + col) * 2;
    }

    float accg[2][4][4], accu[2][4][4];
#pragma unroll
    for (int i = 0; i < 2; i++)
#pragma unroll
        for (int j = 0; j < 4; j++)
#pragma unroll
            for (int q = 0; q < 4; q++) { accg[i][j][q] = 0.f; accu[i][j][q] = 0.f; }

    auto load_tile = [&](int st, int kt) {
        char* base = smem + st * GU_STAGE;
        cpa16(base + adst,        gah + kt * 16);
        cpa16(base + 6144 + adst, gal + kt * 16);
        size_t ko = (size_t)kt * 16 * F_DIM;
        cpa16(base + bdst[0], bsrc[0] + ko);
        cpa16(base + bdst[1], bsrc[1] + ko);
        cp_commit();
    };

    load_tile(0, 0);
    load_tile(1, 1);
    const int KT = H_DIM / 16;   // 64
    int cs = 0;                  // compute stage = kt % 3
#pragma unroll 1
    for (int kt = 0; kt < KT; kt++) {
        if (kt + 1 < KT) cp_wait1(); else cp_wait0();
        __syncthreads();
        if (kt + 2 < KT) {
            int ld = cs + 2; if (ld >= 3) ld -= 3;   // (kt+2) % 3
            load_tile(ld, kt + 2);
        }

        char* base = smem + cs * GU_STAGE;
        uint32_t ah[2][4], al[2][4];
        int r8 = lane & 7, tsel = lane >> 3;
        int acol = (tsel >> 1) * 8;
#pragma unroll
        for (int mt = 0; mt < 2; mt++) {
            int ar = warp_m * 32 + mt * 16 + r8 + (tsel & 1) * 8;
            ldsm_x4(ah[mt], smem_u32(base + (ar * AST + acol) * 2));
            ldsm_x4(al[mt], smem_u32(base + 6144 + (ar * AST + acol) * 2));
        }
        int bkr = (lane & 7) + ((lane >> 3) & 1) * 8;
#pragma unroll
        for (int nt = 0; nt < 4; nt++) {
            int nn = warp_n * 32 + nt * 8;
            uint32_t boff = (uint32_t)(bkr * BST + nn) * 2;
            uint32_t bgh[2], bgl[2], buh[2], bul[2];
            ldsm_x2t(bgh, smem_u32(base + 12288 + 0 * 2304 + boff));
            ldsm_x2t(bgl, smem_u32(base + 12288 + 1 * 2304 + boff));
            ldsm_x2t(buh, smem_u32(base + 12288 + 2 * 2304 + boff));
            ldsm_x2t(bul, smem_u32(base + 12288 + 3 * 2304 + boff));
#pragma unroll
            for (int mt = 0; mt < 2; mt++) {
                mma_bf16(accg[mt][nt], ah[mt], bgh);
                mma_bf16(accg[mt][nt], ah[mt], bgl);
                mma_bf16(accg[mt][nt], al[mt], bgh);
                mma_bf16(accu[mt][nt], ah[mt], buh);
                mma_bf16(accu[mt][nt], ah[mt], bul);
                mma_bf16(accu[mt][nt], al[mt], buh);
            }
        }
        cs = cs + 1; if (cs == 3) cs = 0;
    }

    // epilogue: SwiGLU + split-store
    int gq = lane >> 2, tq = lane & 3;
#pragma unroll
    for (int mt = 0; mt < 2; mt++)
#pragma unroll
        for (int nt = 0; nt < 4; nt++) {
            int fc = f0 + warp_n * 32 + nt * 8 + tq * 2;
#pragma unroll
            for (int h2 = 0; h2 < 2; h2++) {
                int row = rowbase + warp_m * 32 + mt * 16 + gq + h2 * 8;
                if (row < n) {
                    float g0 = accg[mt][nt][h2 * 2],     g1 = accg[mt][nt][h2 * 2 + 1];
                    float u0 = accu[mt][nt][h2 * 2],     u1 = accu[mt][nt][h2 * 2 + 1];
                    float v0 = g0 / (1.f + expf(-g0)) * u0;
                    float v1 = g1 / (1.f + expf(-g1)) * u1;
                    uint32_t hh, ll;
                    split2(v0, v1, hh, ll);
                    size_t basei = (size_t)(off + row) * F_DIM + fc;
                    *(uint32_t*)(g_acth + basei) = hh;
                    *(uint32_t*)(g_actl + basei) = ll;
                }
            }
        }
}

// ---------------- down GEMM: 128x128, BK=16, 3-stage, 2 CTA/SM ---------------
__global__ void __launch_bounds__(256, 2)
down_kernel() {
    extern __shared__ char smem[];
    int e = blockIdx.z;
    int n = g_count[e];
    int rowbase = blockIdx.y * 128;
    if (rowbase >= n) return;
    int off = g_offset[e];
    int h0  = blockIdx.x * 128;
    size_t we = (size_t)e * F_DIM * H_DIM;

    int tid = threadIdx.x, lane = tid & 31, wid = tid >> 5;
    int warp_m = wid >> 1, warp_n = wid & 1;

    int arow = tid >> 1, ahalf = tid & 1;
    int srow = rowbase + arow; if (srow > n - 1) srow = n - 1;
    size_t aoff = (size_t)(off + srow) * F_DIM + ahalf * 8;
    const uint16_t* gah = g_acth + aoff;
    const uint16_t* gal = g_actl + aoff;
    uint32_t adst = (uint32_t)(arow * AST + ahalf * 8) * 2;

    const uint16_t* bsrc[2];
    uint32_t bdst[2];
#pragma unroll
    for (int c = 0; c < 2; c++) {
        int idx = tid + c * 256;
        int brow = idx & 15, t = idx >> 4;
        int mat = t & 1, col = (t >> 1) * 8;
        const uint16_t* base = (mat == 0) ? g_wdh : g_wdl;
        bsrc[c] = base + we + (size_t)brow * H_DIM + h0 + col;
        bdst[c] = 12288 + mat * 4352 + (uint32_t)(brow * BSTD + col) * 2;
    }

    float acc[2][8][4];
#pragma unroll
    for (int i = 0; i < 2; i++)
#pragma unroll
        for (int j = 0; j < 8; j++)
#pragma unroll
            for (int q = 0; q < 4; q++) acc[i][j][q] = 0.f;

    auto load_tile = [&](int st, int kt) {
        char* base = smem + st * DN_STAGE;
        cpa16(base + adst,        gah + kt * 16);
        cpa16(base + 6144 + adst, gal + kt * 16);
        size_t ko = (size_t)kt * 16 * H_DIM;
        cpa16(base + bdst[0], bsrc[0] + ko);
        cpa16(base + bdst[1], bsrc[1] + ko);
        cp_commit();
    };

    load_tile(0, 0);
    load_tile(1, 1);
    const int KT = F_DIM / 16;   // 256
    int cs = 0;
#pragma unroll 1
    for (int kt = 0; kt < KT; kt++) {
        if (kt + 1 < KT) cp_wait1(); else cp_wait0();
        __syncthreads();
        if (kt + 2 < KT) {
            int ld = cs + 2; if (ld >= 3) ld -= 3;
            load_tile(ld, kt + 2);
        }

        char* base = smem + cs * DN_STAGE;
        uint32_t ah[2][4], al[2][4];
        int r8 = lane & 7, tsel = lane >> 3;
        int acol = (tsel >> 1) * 8;
#pragma unroll
        for (int mt = 0; mt < 2; mt++) {
            int ar = warp_m * 32 + mt * 16 + r8 + (tsel & 1) * 8;
            ldsm_x4(ah[mt], smem_u32(base + (ar * AST + acol) * 2));
            ldsm_x4(al[mt], smem_u32(base + 6144 + (ar * AST + acol) * 2));
        }
        int bkr = (lane & 7) + ((lane >> 3) & 1) * 8;
#pragma unroll
        for (int nt = 0; nt < 8; nt++) {
            int nn = warp_n * 64 + nt * 8;
            uint32_t boff = (uint32_t)(bkr * BSTD + nn) * 2;
            uint32_t bh[2], bl[2];
            ldsm_x2t(bh, smem_u32(base + 12288 + boff));
            ldsm_x2t(bl, smem_u32(base + 12288 + 4352 + boff));
#pragma unroll
            for (int mt = 0; mt < 2; mt++) {
                mma_bf16(acc[mt][nt], ah[mt], bh);
                mma_bf16(acc[mt][nt], ah[mt], bl);
                mma_bf16(acc[mt][nt], al[mt], bh);
            }
        }
        cs = cs + 1; if (cs == 3) cs = 0;
    }

    int gq = lane >> 2, tq = lane & 3;
#pragma unroll
    for (int mt = 0; mt < 2; mt++)
#pragma unroll
        for (int nt = 0; nt < 8; nt++) {
            int hc = h0 + warp_n * 64 + nt * 8 + tq * 2;
#pragma unroll
            for (int h2 = 0; h2 < 2; h2++) {
                int row = rowbase + warp_m * 32 + mt * 16 + gq + h2 * 8;
                if (row < n) {
                    float2 v = make_float2(acc[mt][nt][h2 * 2], acc[mt][nt][h2 * 2 + 1]);
                    *(float2*)(g_part + (size_t)(off + row) * H_DIM + hc) = v;
                }
            }
        }
}

// ---------------- combine ----------------------------------------------------
__global__ void combine_kernel(float* __restrict__ out) {
    int idx = blockIdx.x * blockDim.x + threadIdx.x;
    if (idx >= T_TOK * H_DIM) return;
    int t = idx >> 10;
    int h = idx & 1023;
    int   s0 = g_slot_of[t * 2 + 0];
    int   s1 = g_slot_of[t * 2 + 1];
    float w0 = g_tok_w[t * 2 + 0];
    float w1 = g_tok_w[t * 2 + 1];
    out[idx] = w0 * g_part[(size_t)s0 * H_DIM + h] +
               w1 * g_part[(size_t)s1 * H_DIM + h];
}

// ---------------- launch -----------------------------------------------------
extern "C" void kernel_launch(void* const* d_in, const int* in_sizes, int n_in,
                              void* d_out, int out_size) {
    const float* x      = (const float*)d_in[0];
    const float* gate_w = (const float*)d_in[1];
    const float* w_gate = (const float*)d_in[2];
    const float* w_up   = (const float*)d_in[3];
    const float* w_down = (const float*)d_in[4];
    float* out = (float*)d_out;

    cudaFuncSetAttribute(gateup_kernel, cudaFuncAttributeMaxDynamicSharedMemorySize, GU_SMEM);
    cudaFuncSetAttribute(down_kernel,   cudaFuncAttributeMaxDynamicSharedMemorySize, DN_SMEM);

    zero_counts_kernel<<<1, 32>>>();
    router_kernel<<<T_TOK / 8, 256>>>(x, gate_w);
    scan_scatter_kernel<<<1, 256>>>();
    split_x_kernel<<<(T_TOK * H_DIM / 4) / 256, 256>>>(x);
    split_weights_kernel<<<1184, 256>>>(w_gate, w_up, w_down);
    gateup_kernel<<<dim3(F_DIM / 64, NSLOT / 128, N_EXP), 256, GU_SMEM>>>();
    down_kernel<<<dim3(H_DIM / 128, NSLOT / 128, N_EXP), 256, DN_SMEM>>>();
    combine_kernel<<<(T_TOK * H_DIM) / 256, 256>>>(out);
}